// round 14
// baseline (speedup 1.0000x reference)
#include <cuda_runtime.h>
#include <cuda_fp16.h>

#define B_ 2
#define S_ 4096
#define C_ 512
#define H_ 8
#define D_ 64

// Scratch (allocation-free rule: __device__ globals)
__device__ __align__(16) __half g_h [B_ * S_ * C_];   // hidden fp16
__device__ __align__(16) __half g_wq[C_ * C_];
__device__ __align__(16) __half g_wk[C_ * C_];
__device__ __align__(16) __half g_wv[C_ * C_];
__device__ __align__(16) __half g_wo[C_ * C_];
__device__ __align__(16) __half g_q [B_ * S_ * C_];   // pre-scaled by 0.125*log2e
__device__ __align__(16) __half g_k [B_ * S_ * C_];
__device__ __align__(16) __half g_v [B_ * S_ * C_];
__device__ __align__(16) __half g_at[B_ * S_ * C_];

// ---------------------------------------------------------------------------
__device__ __forceinline__ void mma_f16(float d[4], const unsigned a[4],
                                        unsigned b0, unsigned b1) {
    asm volatile(
        "mma.sync.aligned.m16n8k16.row.col.f32.f16.f16.f32 "
        "{%0,%1,%2,%3}, {%4,%5,%6,%7}, {%8,%9}, {%0,%1,%2,%3};\n"
        : "+f"(d[0]), "+f"(d[1]), "+f"(d[2]), "+f"(d[3])
        : "r"(a[0]), "r"(a[1]), "r"(a[2]), "r"(a[3]), "r"(b0), "r"(b1));
}
__device__ __forceinline__ unsigned pack2(float x, float y) {
    __half2 h = __floats2half2_rn(x, y);
    return *(unsigned*)&h;
}
__device__ __forceinline__ unsigned ex2h2(unsigned x) {
    unsigned r;
    asm("ex2.approx.f16x2 %0, %1;" : "=r"(r) : "r"(x));
    return r;
}
__device__ __forceinline__ void ldsm4(unsigned r[4], const __half* p) {
    unsigned a = (unsigned)__cvta_generic_to_shared(p);
    asm volatile(
        "ldmatrix.sync.aligned.m8n8.x4.shared.b16 {%0,%1,%2,%3}, [%4];\n"
        : "=r"(r[0]), "=r"(r[1]), "=r"(r[2]), "=r"(r[3]) : "r"(a));
}
__device__ __forceinline__ void ldsm4t(unsigned r[4], const __half* p) {
    unsigned a = (unsigned)__cvta_generic_to_shared(p);
    asm volatile(
        "ldmatrix.sync.aligned.m8n8.x4.trans.shared.b16 {%0,%1,%2,%3}, [%4];\n"
        : "=r"(r[0]), "=r"(r[1]), "=r"(r[2]), "=r"(r[3]) : "r"(a));
}
__device__ __forceinline__ void cp16(__half* dst, const __half* src) {
    unsigned d = (unsigned)__cvta_generic_to_shared(dst);
    asm volatile("cp.async.cg.shared.global [%0], [%1], 16;\n"
                 :: "r"(d), "l"(src));
}
__device__ __forceinline__ void cp_commit() {
    asm volatile("cp.async.commit_group;\n");
}
__device__ __forceinline__ void cp_wait0() {
    asm volatile("cp.async.wait_group 0;\n");
}
__device__ __forceinline__ void cp_wait1() {
    asm volatile("cp.async.wait_group 1;\n");
}

// ---------------------------------------------------------------------------
// fp32 -> fp16 converts
// ---------------------------------------------------------------------------
__global__ __launch_bounds__(256) void f2h_kernel(
    const float* __restrict__ in, __half* __restrict__ out, int n4)
{
    int i = blockIdx.x * blockDim.x + threadIdx.x;
    if (i < n4) {
        float4 v = ((const float4*)in)[i];
        __half2 a = __floats2half2_rn(v.x, v.y);
        __half2 b = __floats2half2_rn(v.z, v.w);
        ((uint2*)out)[i] = make_uint2(*(unsigned*)&a, *(unsigned*)&b);
    }
}
__global__ __launch_bounds__(256) void f2h4_kernel(
    const float* __restrict__ i0, const float* __restrict__ i1,
    const float* __restrict__ i2, const float* __restrict__ i3,
    __half* __restrict__ o0, __half* __restrict__ o1,
    __half* __restrict__ o2, __half* __restrict__ o3, int n4)
{
    const float* in = (blockIdx.y == 0) ? i0 : (blockIdx.y == 1) ? i1
                    : (blockIdx.y == 2) ? i2 : i3;
    __half* out = (blockIdx.y == 0) ? o0 : (blockIdx.y == 1) ? o1
                : (blockIdx.y == 2) ? o2 : o3;
    int i = blockIdx.x * blockDim.x + threadIdx.x;
    if (i < n4) {
        float4 v = ((const float4*)in)[i];
        __half2 a = __floats2half2_rn(v.x, v.y);
        __half2 b = __floats2half2_rn(v.z, v.w);
        ((uint2*)out)[i] = make_uint2(*(unsigned*)&a, *(unsigned*)&b);
    }
}

// ---------------------------------------------------------------------------
// Core GEMM body: CTA 128x128, 4 warps 2m x 2n (warp tile 64x64), BK=64,
// cp.async 3-stage (wait_group 1). 128 MMAs per warp-epoch vs 32 ldsm.
// ---------------------------------------------------------------------------
template <bool F32OUT>
__device__ __forceinline__ void gemm_body(
    const __half* __restrict__ A, const __half* __restrict__ W,
    const float* __restrict__ bias, void* __restrict__ Cout,
    int M, int N, int K, float oscale, int m0, int n0)
{
    extern __shared__ __half smp[];
    auto Asb = [&](int st) { return smp + st * 18432; };
    auto Wsb = [&](int st) { return smp + st * 18432 + 9216; };

    const int tid = threadIdx.x;
    const int w = tid >> 5, lane = tid & 31;
    const int qr = lane >> 2, qc = lane & 3;
    const int wm = w & 1, wn = w >> 1;          // 2 m-warps x 2 n-warps

    auto issue = [&](int kt, int st) {
        int k0 = kt * 64;
        __half* ad = Asb(st);
        __half* wd = Wsb(st);
        #pragma unroll
        for (int u = 0; u < 8; ++u) {           // A: 128 rows x 8 chunks
            int i = tid + u * 128, r = i >> 3, c = i & 7;
            cp16(&ad[r * 72 + c * 8],
                 &A[(size_t)(m0 + r) * K + k0 + c * 8]);
        }
        #pragma unroll
        for (int u = 0; u < 8; ++u) {           // W: 128 rows x 8 chunks
            int i = tid + u * 128, r = i >> 3, c = i & 7;
            cp16(&wd[r * 72 + c * 8],
                 &W[(size_t)(n0 + r) * K + k0 + c * 8]);
        }
        cp_commit();
    };

    const int NK = K / 64;                      // 8 epochs
    issue(0, 0);
    issue(1, 1);

    float acc[4][8][4] = {};                    // [mt 16-row][nt 8-col]

    int st = 0, st2 = 2;                        // cyclic stage counters
    for (int kt = 0; kt < NK; ++kt) {
        if (kt + 1 < NK) cp_wait1(); else cp_wait0();
        __syncthreads();   // all warps done with prior epoch -> refill safe
        if (kt + 2 < NK) issue(kt + 2, st2);

        const __half* Ab = Asb(st);
        const __half* Wb = Wsb(st);

        #pragma unroll
        for (int half = 0; half < 2; ++half) {
            const int kc = half * 32;
            unsigned wb[8][4];
            #pragma unroll
            for (int nt = 0; nt < 8; ++nt)
                ldsm4(wb[nt],
                      &Wb[(wn * 64 + nt * 8 + (lane & 7)) * 72 +
                          kc + (lane >> 3) * 8]);

            #pragma unroll
            for (int ks = 0; ks < 2; ++ks) {
                unsigned af[4][4];
                #pragma unroll
                for (int mt = 0; mt < 4; ++mt)
                    ldsm4(af[mt],
                          &Ab[(wm * 64 + mt * 16 + (lane & 15)) * 72 +
                              kc + ks * 16 + (lane >> 4) * 8]);
                #pragma unroll
                for (int mt = 0; mt < 4; ++mt)
                    #pragma unroll
                    for (int nt = 0; nt < 8; ++nt)
                        mma_f16(acc[mt][nt], af[mt],
                                wb[nt][2 * ks], wb[nt][2 * ks + 1]);
            }
        }
        st = (st == 2) ? 0 : st + 1;
        st2 = (st2 == 2) ? 0 : st2 + 1;
    }

    #pragma unroll
    for (int mt = 0; mt < 4; ++mt) {
        int row = m0 + wm * 64 + mt * 16 + qr;
        #pragma unroll
        for (int nt = 0; nt < 8; ++nt) {
            int col = n0 + wn * 64 + nt * 8 + 2 * qc;
            if (F32OUT) {
                float b0 = bias[col], b1 = bias[col + 1];
                *(float2*)&((float*)Cout)[(size_t)row * N + col] =
                    make_float2(acc[mt][nt][0] + b0, acc[mt][nt][1] + b1);
                *(float2*)&((float*)Cout)[(size_t)(row + 8) * N + col] =
                    make_float2(acc[mt][nt][2] + b0, acc[mt][nt][3] + b1);
            } else {
                *(__half2*)&((__half*)Cout)[(size_t)row * N + col] =
                    __floats2half2_rn(acc[mt][nt][0] * oscale,
                                      acc[mt][nt][1] * oscale);
                *(__half2*)&((__half*)Cout)[(size_t)(row + 8) * N + col] =
                    __floats2half2_rn(acc[mt][nt][2] * oscale,
                                      acc[mt][nt][3] * oscale);
            }
        }
    }
}

// Fused QKV: blockIdx.z selects weight/output; Q gets softmax pre-scale.
__global__ __launch_bounds__(128, 2) void gemm_qkv(
    const __half* __restrict__ A,
    const __half* __restrict__ W0, const __half* __restrict__ W1,
    const __half* __restrict__ W2,
    __half* __restrict__ O0, __half* __restrict__ O1, __half* __restrict__ O2,
    int M, int N, int K)
{
    const int z = blockIdx.z;
    const __half* W = (z == 0) ? W0 : (z == 1) ? W1 : W2;
    __half* Cout = (z == 0) ? O0 : (z == 1) ? O1 : O2;
    const float oscale = (z == 0) ? 0.1803368801111244f : 1.0f;
    gemm_body<false>(A, W, nullptr, Cout, M, N, K, oscale,
                     blockIdx.y * 128, blockIdx.x * 128);
}

// Output projection: fp32 out + bias.
__global__ __launch_bounds__(128, 2) void gemm_out(
    const __half* __restrict__ A, const __half* __restrict__ W,
    const float* __restrict__ bias, float* __restrict__ Cout,
    int M, int N, int K)
{
    gemm_body<true>(A, W, bias, Cout, M, N, K, 1.0f,
                    blockIdx.y * 128, blockIdx.x * 128);
}

// ---------------------------------------------------------------------------
// Flash attention fp16 (R12-proven, unchanged): CTA = 128 q-rows, 4 warps,
// kv-tile 128 per epoch, Q pre-scaled, ex2-P-in-fragment, ones-MMA row sums.
// ---------------------------------------------------------------------------
__global__ __launch_bounds__(128, 2) void attn_f16(
    const __half* __restrict__ Q, const __half* __restrict__ K,
    const __half* __restrict__ V, __half* __restrict__ O)
{
    extern __shared__ __half smp[];
    auto Ksb = [&](int st) { return smp + st * 18432; };          // 128*72
    auto Vsb = [&](int st) { return smp + st * 18432 + 9216; };   // 128*72

    const int tid = threadIdx.x;
    const int w = tid >> 5, lane = tid & 31;
    const int qr = lane >> 2, qc = lane & 3;
    const int q0 = blockIdx.x * 128;
    const int h = blockIdx.y, b = blockIdx.z;
    const size_t base = (size_t)b * S_ * C_ + (size_t)h * D_;

    auto issue = [&](int k0, int st) {
        __half* kd = Ksb(st);
        __half* vd = Vsb(st);
        #pragma unroll
        for (int u = 0; u < 16; ++u) {
            int i = tid + u * 128;
            int j = i & 1023, r = j >> 3, c = j & 7;
            const __half* src = (i < 1024) ? K : V;
            __half* dst = (i < 1024) ? kd : vd;
            cp16(&dst[r * 72 + c * 8],
                 &src[base + (size_t)(k0 + r) * C_ + c * 8]);
        }
        cp_commit();
    };

    issue(0, 0);

    unsigned qf[2][4][4];
    #pragma unroll
    for (int s = 0; s < 2; ++s) {
        const __half* qp0 = Q + base + (size_t)(q0 + w * 32 + s * 16 + qr) * C_;
        const __half* qp8 = qp0 + 8 * C_;
        #pragma unroll
        for (int ks = 0; ks < 4; ++ks) {
            qf[s][ks][0] = *(const unsigned*)&qp0[ks * 16 + 2 * qc];
            qf[s][ks][1] = *(const unsigned*)&qp8[ks * 16 + 2 * qc];
            qf[s][ks][2] = *(const unsigned*)&qp0[ks * 16 + 8 + 2 * qc];
            qf[s][ks][3] = *(const unsigned*)&qp8[ks * 16 + 8 + 2 * qc];
        }
    }

    const unsigned ones = (qr == 0) ? 0x3C003C00u : 0u;

    float lacc[2][4] = {};
    float o[2][8][4] = {};

    const int r8 = lane & 7, t8 = lane >> 3;

    const int NT = S_ / 128;
    for (int t = 0; t < NT; ++t) {
        cp_wait0();
        __syncthreads();
        if (t + 1 < NT) issue((t + 1) * 128, (t + 1) & 1);

        #pragma unroll
        for (int hf = 0; hf < 2; ++hf) {
            const __half* Kst = Ksb(t & 1) + hf * (64 * 72);
            const __half* Vst = Vsb(t & 1) + hf * (64 * 72);

            unsigned pa_[2][4][4];
            #pragma unroll
            for (int nt = 0; nt < 8; ++nt) {
                unsigned kb0[4], kb1[4];
                const __half* rp = &Kst[(nt * 8 + r8) * 72 + t8 * 8];
                ldsm4(kb0, rp);
                ldsm4(kb1, rp + 32);
                const int kk = nt >> 1, hi = (nt & 1) ? 2 : 0;
                #pragma unroll
                for (int s = 0; s < 2; ++s) {
                    float sa[4] = {};
                    mma_f16(sa, qf[s][0], kb0[0], kb0[1]);
                    mma_f16(sa, qf[s][1], kb0[2], kb0[3]);
                    mma_f16(sa, qf[s][2], kb1[0], kb1[1]);
                    mma_f16(sa, qf[s][3], kb1[2], kb1[3]);
                    pa_[s][kk][hi]     = ex2h2(pack2(sa[0], sa[1]));
                    pa_[s][kk][hi + 1] = ex2h2(pack2(sa[2], sa[3]));
                }
            }

            #pragma unroll
            for (int s = 0; s < 2; ++s)
                #pragma unroll
                for (int kk = 0; kk < 4; ++kk)
                    mma_f16(lacc[s], pa_[s][kk], ones, ones);

            #pragma unroll
            for (int nt = 0; nt < 8; ++nt) {
                unsigned vb0[4], vb1[4];
                ldsm4t(vb0, &Vst[(t8 * 8 + r8) * 72 + nt * 8]);
                ldsm4t(vb1, &Vst[(32 + t8 * 8 + r8) * 72 + nt * 8]);
                #pragma unroll
                for (int s = 0; s < 2; ++s) {
                    mma_f16(o[s][nt], pa_[s][0], vb0[0], vb0[1]);
                    mma_f16(o[s][nt], pa_[s][1], vb0[2], vb0[3]);
                    mma_f16(o[s][nt], pa_[s][2], vb1[0], vb1[1]);
                    mma_f16(o[s][nt], pa_[s][3], vb1[2], vb1[3]);
                }
            }
        }
    }

    #pragma unroll
    for (int s = 0; s < 2; ++s) {
        float L0 = __shfl_sync(0xffffffffu, lacc[s][0], lane & 28);
        float L1 = __shfl_sync(0xffffffffu, lacc[s][2], lane & 28);
        float inv0 = 1.0f / L0, inv1 = 1.0f / L1;
        int row = q0 + w * 32 + s * 16 + qr;
        #pragma unroll
        for (int nt = 0; nt < 8; ++nt) {
            int col = nt * 8 + 2 * qc;
            *(__half2*)&O[base + (size_t)row * C_ + col] =
                __floats2half2_rn(o[s][nt][0] * inv0, o[s][nt][1] * inv0);
            *(__half2*)&O[base + (size_t)(row + 8) * C_ + col] =
                __floats2half2_rn(o[s][nt][2] * inv1, o[s][nt][3] * inv1);
        }
    }
}

// ---------------------------------------------------------------------------
extern "C" void kernel_launch(void* const* d_in, const int* in_sizes, int n_in,
                              void* d_out, int out_size)
{
    const float* hidden = (const float*)d_in[0];
    const float* Wq = (const float*)d_in[1];
    const float* Wk = (const float*)d_in[2];
    const float* Wv = (const float*)d_in[3];
    const float* Wo = (const float*)d_in[4];
    const float* bo = (const float*)d_in[5];
    float* out = (float*)d_out;

    __half *hp, *wqp, *wkp, *wvp, *wop, *qp, *kp, *vp, *ap;
    cudaGetSymbolAddress((void**)&hp, g_h);
    cudaGetSymbolAddress((void**)&wqp, g_wq);
    cudaGetSymbolAddress((void**)&wkp, g_wk);
    cudaGetSymbolAddress((void**)&wvp, g_wv);
    cudaGetSymbolAddress((void**)&wop, g_wo);
    cudaGetSymbolAddress((void**)&qp, g_q);
    cudaGetSymbolAddress((void**)&kp, g_k);
    cudaGetSymbolAddress((void**)&vp, g_v);
    cudaGetSymbolAddress((void**)&ap, g_at);

    const int GEMM_SMEM = 3 * 18432 * (int)sizeof(__half);  // 110592 B
    const int ATTN_SMEM = 2 * 18432 * (int)sizeof(__half);  // 73728 B
    static bool attr_set = false;
    if (!attr_set) {
        cudaFuncSetAttribute(gemm_qkv,
                             cudaFuncAttributeMaxDynamicSharedMemorySize,
                             GEMM_SMEM);
        cudaFuncSetAttribute(gemm_out,
                             cudaFuncAttributeMaxDynamicSharedMemorySize,
                             GEMM_SMEM);
        cudaFuncSetAttribute(attn_f16,
                             cudaFuncAttributeMaxDynamicSharedMemorySize,
                             ATTN_SMEM);
        attr_set = true;
    }

    const int nh4 = B_ * S_ * C_ / 4;
    const int nw4 = C_ * C_ / 4;
    f2h_kernel<<<nh4 / 256, 256>>>(hidden, hp, nh4);
    f2h4_kernel<<<dim3(nw4 / 256, 4), 256>>>(Wq, Wk, Wv, Wo,
                                             wqp, wkp, wvp, wop, nw4);

    dim3 gQKV(C_ / 128, (B_ * S_) / 128, 3);  // (4, 64, 3)
    gemm_qkv<<<gQKV, 128, GEMM_SMEM>>>(hp, wqp, wkp, wvp, qp, kp, vp,
                                       B_ * S_, C_, C_);

    attn_f16<<<dim3(S_ / 128, H_, B_), 128, ATTN_SMEM>>>(qp, kp, vp, ap);

    dim3 gOut(C_ / 128, (B_ * S_) / 128);     // (4, 64)
    gemm_out<<<gOut, 128, GEMM_SMEM>>>(ap, wop, bo, out, B_ * S_, C_, C_);
}